// round 14
// baseline (speedup 1.0000x reference)
#include <cuda_runtime.h>
#include <cuda_fp16.h>
#include <cstdint>
#include <math_constants.h>

// Fixed dataset shape: N=50000, E=800000, Fin=128, H=C=64
#define NMAX 50048
#define EMAX 800000
#define HC   64

typedef unsigned long long ull;

// ---------------- scratch (__device__ globals; no allocation allowed) --------------
__device__ __half2 g_h2[NMAX * 32];   // h = x @ W, fp16x2 (channel pairs)
__device__ float   g_x2[NMAX * HC];   // layer-2 input (fp32)
__device__ float   g_as[NMAX];        // alpha_src per node
__device__ float   g_ad[NMAX];        // alpha_dst per node
__device__ int     g_src[EMAX];       // edge src
__device__ int     g_dst[EMAX];       // edge dst
__device__ int     g_rank[EMAX];      // rank of edge within its dst row
__device__ int     g_deg[NMAX];       // in-degree histogram (zeroed by k_scan after use)
__device__ int     g_row[NMAX + 4];   // CSR row starts (int4-padded)
__device__ int     g_ssrc[EMAX];      // src ids grouped by dst

// packed f32x2 fma (sm_103a; ptxas never emits FFMA2 from C++)
__device__ __forceinline__ void fma2(ull& acc, ull x2, ull w2) {
    asm("fma.rn.f32x2 %0, %1, %2, %0;" : "+l"(acc) : "l"(x2), "l"(w2));
}
__device__ __forceinline__ ull dup2(float f) {
    ull r;
    asm("mov.b64 %0, {%1, %1};" : "=l"(r) : "f"(f));
    return r;
}

// ---------------- GEMM body (R12 proven): prefetch + transposed Xs + FFMA2 ----------
template <int K>
__device__ void gemm_body(const float* __restrict__ X, const float* __restrict__ W,
                          const float* __restrict__ avs, const float* __restrict__ avd,
                          int N, int bid) {
    const int XS = 132;                  // stride: 128 + 4 pad
    __shared__ float Xs[32 * XS];        // [k][row] transposed
    __shared__ float Ws[32 * 64];        // [k][col]
    int tid = threadIdx.x;
    int tx = tid & 15, ty = tid >> 4;
    int row0 = bid * 128;

    int xrow = tid >> 3;
    int xk   = (tid & 7) * 4;
    float4 xst[4];
    float4 wst[2];

    auto stage = [&](int k0) {
#pragma unroll
        for (int p = 0; p < 4; p++) {
            int row = row0 + xrow + p * 32;
            xst[p] = (row < N)
                ? *reinterpret_cast<const float4*>(&X[(size_t)row * K + k0 + xk])
                : make_float4(0.f, 0.f, 0.f, 0.f);
        }
#pragma unroll
        for (int j = 0; j < 2; j++) {
            int f = tid + j * 256;
            int k_l = f >> 4, c4 = (f & 15) * 4;
            wst[j] = *reinterpret_cast<const float4*>(&W[(size_t)(k0 + k_l) * 64 + c4]);
        }
    };
    auto commit = [&]() {
#pragma unroll
        for (int p = 0; p < 4; p++) {
            int row_l = xrow + p * 32;
            Xs[(xk + 0) * XS + row_l] = xst[p].x;
            Xs[(xk + 1) * XS + row_l] = xst[p].y;
            Xs[(xk + 2) * XS + row_l] = xst[p].z;
            Xs[(xk + 3) * XS + row_l] = xst[p].w;
        }
#pragma unroll
        for (int j = 0; j < 2; j++) {
            int f = tid + j * 256;
            int k_l = f >> 4, c4 = (f & 15) * 4;
            *reinterpret_cast<float4*>(&Ws[k_l * 64 + c4]) = wst[j];
        }
    };

    ull acc[4][4];
#pragma unroll
    for (int rp = 0; rp < 4; rp++)
#pragma unroll
        for (int c = 0; c < 4; c++) acc[rp][c] = 0ull;

    stage(0);
    const int NT = K / 32;
#pragma unroll
    for (int t = 0; t < NT; t++) {
        commit();
        __syncthreads();
        if (t + 1 < NT) stage((t + 1) * 32);   // LDGs overlap compute below
#pragma unroll
        for (int k = 0; k < 32; k++) {
            ulonglong2 xa = *reinterpret_cast<const ulonglong2*>(&Xs[k * XS + ty * 8]);
            ulonglong2 xb = *reinterpret_cast<const ulonglong2*>(&Xs[k * XS + ty * 8 + 4]);
            float4 wv = *reinterpret_cast<const float4*>(&Ws[k * 64 + tx * 4]);
            ull w2[4];
            w2[0] = dup2(wv.x); w2[1] = dup2(wv.y);
            w2[2] = dup2(wv.z); w2[3] = dup2(wv.w);
#pragma unroll
            for (int c = 0; c < 4; c++) {
                fma2(acc[0][c], xa.x, w2[c]);
                fma2(acc[1][c], xa.y, w2[c]);
                fma2(acc[2][c], xb.x, w2[c]);
                fma2(acc[3][c], xb.y, w2[c]);
            }
        }
        __syncthreads();
    }

    float a[8][4];
#pragma unroll
    for (int rp = 0; rp < 4; rp++)
#pragma unroll
        for (int c = 0; c < 4; c++) {
            float lo, hi;
            asm("mov.b64 {%0, %1}, %2;" : "=f"(lo), "=f"(hi) : "l"(acc[rp][c]));
            a[rp * 2 + 0][c] = lo;
            a[rp * 2 + 1][c] = hi;
        }

    float avs4[4], avd4[4];
#pragma unroll
    for (int j = 0; j < 4; j++) {
        avs4[j] = __ldg(&avs[tx * 4 + j]);
        avd4[j] = __ldg(&avd[tx * 4 + j]);
    }
#pragma unroll
    for (int i = 0; i < 8; i++) {
        int row = row0 + ty * 8 + i;
        float s = a[i][0] * avs4[0] + a[i][1] * avs4[1] + a[i][2] * avs4[2] + a[i][3] * avs4[3];
        float d = a[i][0] * avd4[0] + a[i][1] * avd4[1] + a[i][2] * avd4[2] + a[i][3] * avd4[3];
#pragma unroll
        for (int o = 8; o > 0; o >>= 1) {
            s += __shfl_down_sync(0xFFFFFFFFu, s, o, 16);
            d += __shfl_down_sync(0xFFFFFFFFu, d, o, 16);
        }
        if (tx == 0 && row < N) { g_as[row] = s; g_ad[row] = d; }
        if (row < N) {
            __half2 h01 = __floats2half2_rn(a[i][0], a[i][1]);
            __half2 h23 = __floats2half2_rn(a[i][2], a[i][3]);
            uint2 pk = make_uint2(*reinterpret_cast<uint32_t*>(&h01),
                                  *reinterpret_cast<uint32_t*>(&h23));
            *reinterpret_cast<uint2*>(&g_h2[row * 32 + tx * 2]) = pk;
        }
    }
}

// ---------------- ingest body: dtype-detect + convert + histogram + rank -------------
__device__ void ingest_body(const void* __restrict__ eiv, int E, int N, int bid) {
    int i = bid * 256 + threadIdx.x;
    int e0 = i * 2;
    long long v0 = 0, v1 = 0;
    int ok = 1;
    if (e0 + 1 < E) {
        longlong2 v = ((const longlong2*)eiv)[i];
        v0 = v.x; v1 = v.y;
        ok = (v0 >= 0 && v0 < (long long)N && v1 >= 0 && v1 < (long long)N) ? 1 : 0;
    } else if (e0 < E) {
        v0 = ((const long long*)eiv)[e0];
        ok = (v0 >= 0 && v0 < (long long)N) ? 1 : 0;
    }
    int all64 = __syncthreads_and(ok);
    if (e0 >= E) return;
    int s0, s1 = 0, d0, d1 = 0;
    int has1 = (e0 + 1 < E);
    if (all64) {
        const long long* e = (const long long*)eiv;
        s0 = (int)v0;
        d0 = (int)e[E + e0];
        if (has1) { s1 = (int)v1; d1 = (int)e[E + e0 + 1]; }
    } else {
        const int* e = (const int*)eiv;
        s0 = e[e0];
        d0 = e[E + e0];
        if (has1) { s1 = e[e0 + 1]; d1 = e[E + e0 + 1]; }
    }
    s0 = min(max(s0, 0), N - 1); d0 = min(max(d0, 0), N - 1);
    g_src[e0] = s0; g_dst[e0] = d0;
    g_rank[e0] = atomicAdd(&g_deg[d0], 1);
    if (has1) {
        s1 = min(max(s1, 0), N - 1); d1 = min(max(d1, 0), N - 1);
        g_src[e0 + 1] = s1; g_dst[e0 + 1] = d1;
        g_rank[e0 + 1] = atomicAdd(&g_deg[d1], 1);
    }
}

// fat kernel: gemm1 blocks [0, ngemm) + ingest blocks [ngemm, ...)
__global__ __launch_bounds__(256)
void k_fat(const float* __restrict__ X, const float* __restrict__ W,
           const float* __restrict__ avs, const float* __restrict__ avd,
           const void* __restrict__ eiv, int N, int E, int ngemm) {
    if ((int)blockIdx.x < ngemm)
        gemm_body<128>(X, W, avs, avd, N, blockIdx.x);
    else
        ingest_body(eiv, E, N, blockIdx.x - ngemm);
}

__global__ __launch_bounds__(256)
void k_gemm2(const float* __restrict__ X, const float* __restrict__ W,
             const float* __restrict__ avs, const float* __restrict__ avd, int N) {
    gemm_body<64>(X, W, avs, avd, N, blockIdx.x);
}

// ---------------- scan (self-cleaning: zeroes g_deg after reading) -------------------
__global__ void k_scan() {
    __shared__ int warp_red[32];
    __shared__ int s_carry;
    int tid = threadIdx.x, lane = tid & 31, wid = tid >> 5;
    if (tid == 0) s_carry = 0;
    __syncthreads();
    int4* deg4 = (int4*)g_deg;
    int4* row4 = (int4*)g_row;
    const int total4 = NMAX / 4;
    for (int base = 0; base < total4; base += 1024) {
        int idx = base + tid;
        int4 v = (idx < total4) ? deg4[idx] : make_int4(0, 0, 0, 0);
        if (idx < total4) deg4[idx] = make_int4(0, 0, 0, 0);
        int s = v.x + v.y + v.z + v.w;
        int x = s;
#pragma unroll
        for (int o = 1; o < 32; o <<= 1) {
            int t = __shfl_up_sync(0xFFFFFFFFu, x, o);
            if (lane >= o) x += t;
        }
        if (lane == 31) warp_red[wid] = x;
        __syncthreads();
        if (wid == 0) {
            int w = warp_red[lane];
#pragma unroll
            for (int o = 1; o < 32; o <<= 1) {
                int t = __shfl_up_sync(0xFFFFFFFFu, w, o);
                if (lane >= o) w += t;
            }
            warp_red[lane] = w;
        }
        __syncthreads();
        int wsum = (wid > 0) ? warp_red[wid - 1] : 0;
        int incl = x + wsum;
        int carry = s_carry;
        if (idx < total4) {
            int e0 = carry + incl - s;
            int4 r;
            r.x = e0;
            r.y = e0 + v.x;
            r.z = e0 + v.x + v.y;
            r.w = e0 + v.x + v.y + v.z;
            row4[idx] = r;
        }
        __syncthreads();
        if (tid == 1023) s_carry = carry + incl;
        __syncthreads();
    }
}

// atomic-free scatter, 8 edges/thread (2x int4 loads; MLP=8 on gathers/stores)
__global__ void k_scatter(int E) {
    int i = blockIdx.x * 256 + threadIdx.x;
    int nvec = E >> 3;
    if (i < nvec) {
        const int4* d4 = (const int4*)g_dst;
        const int4* r4 = (const int4*)g_rank;
        const int4* s4 = (const int4*)g_src;
        int4 da = d4[2 * i], db = d4[2 * i + 1];
        int4 ra = r4[2 * i], rb = r4[2 * i + 1];
        int4 sa = s4[2 * i], sb = s4[2 * i + 1];
        int b0 = g_row[da.x], b1 = g_row[da.y], b2 = g_row[da.z], b3 = g_row[da.w];
        int b4 = g_row[db.x], b5 = g_row[db.y], b6 = g_row[db.z], b7 = g_row[db.w];
        g_ssrc[b0 + ra.x] = sa.x;
        g_ssrc[b1 + ra.y] = sa.y;
        g_ssrc[b2 + ra.z] = sa.z;
        g_ssrc[b3 + ra.w] = sa.w;
        g_ssrc[b4 + rb.x] = sb.x;
        g_ssrc[b5 + rb.y] = sb.y;
        g_ssrc[b6 + rb.z] = sb.z;
        g_ssrc[b7 + rb.w] = sb.w;
    } else if (i == nvec) {
        for (int e = nvec * 8; e < E; e++)
            g_ssrc[g_row[g_dst[e]] + g_rank[e]] = g_src[e];
    }
}

// ---------------- fused GAT aggregation: quarter-warp LDG.128 scheme ----------------
// Lanes split 4 ways: quarter q serves edge j = u + v*4 + q; each lane loads uint4
// (8 fp16 channels) of its edge's h-row — one warp LDG.128 covers 4 edges.
// Shift-free softmax (scores O(1); fp32 exp cannot overflow); p=0 self-gates
// out-of-range edges (no predicates in the inner loop).
__global__ void k_gat(const float* __restrict__ bias, float* __restrict__ outbuf,
                      int do_relu, int N) {
    int warp = (blockIdx.x * blockDim.x + threadIdx.x) >> 5;
    int lane = threadIdx.x & 31;
    if (warp >= N) return;
    int beg = g_row[warp], end = g_row[warp + 1];
    float ad = g_ad[warp];
    const uint4* h4v = (const uint4*)g_h2;   // 8 uint4 per node row (128 B)
    int qx = lane & 7;                        // uint4 index within the row
    int quarter = lane >> 3;                  // which of 4 concurrent edges

    float acc[8] = {0.f, 0.f, 0.f, 0.f, 0.f, 0.f, 0.f, 0.f};  // channels qx*8..+7
    float ssum = 0.f;
    for (int base = beg; base < end; base += 32) {
        int i = base + lane;
        float p = 0.f;
        int off = 0;
        if (i < end) {
            int s = g_ssrc[i];
            float e = g_as[s] + ad;
            e = (e > 0.f) ? e : 0.2f * e;      // LeakyReLU(0.2)
            p = __expf(e);
            ssum += p;
            off = s * 8;                        // row offset in uint4 units
        }
        int cnt = min(32, end - base);
        for (int u = 0; u < cnt; u += 16) {     // 16 edges per iter = 4 LDG.128 (MLP 4)
            uint4 hw[4]; float pw[4];
#pragma unroll
            for (int v = 0; v < 4; v++) {
                int j = u + v * 4 + quarter;               // this quarter's edge
                pw[v] = __shfl_sync(0xFFFFFFFFu, p, j & 31);   // p=0 beyond cnt
                int ov = __shfl_sync(0xFFFFFFFFu, off, j & 31);
                hw[v] = h4v[ov + qx];
            }
#pragma unroll
            for (int v = 0; v < 4; v++) {
                float2 f0 = __half22float2(*reinterpret_cast<__half2*>(&hw[v].x));
                float2 f1 = __half22float2(*reinterpret_cast<__half2*>(&hw[v].y));
                float2 f2 = __half22float2(*reinterpret_cast<__half2*>(&hw[v].z));
                float2 f3 = __half22float2(*reinterpret_cast<__half2*>(&hw[v].w));
                acc[0] += pw[v] * f0.x; acc[1] += pw[v] * f0.y;
                acc[2] += pw[v] * f1.x; acc[3] += pw[v] * f1.y;
                acc[4] += pw[v] * f2.x; acc[5] += pw[v] * f2.y;
                acc[6] += pw[v] * f3.x; acc[7] += pw[v] * f3.y;
            }
        }
    }
#pragma unroll
    for (int o = 16; o > 0; o >>= 1)
        ssum += __shfl_xor_sync(0xFFFFFFFFu, ssum, o);

    // merge the 4 quarters' partial channel sums (two xor levels: 8, 16)
#pragma unroll
    for (int c = 0; c < 8; c++) {
        acc[c] += __shfl_xor_sync(0xFFFFFFFFu, acc[c], 8);
        acc[c] += __shfl_xor_sync(0xFFFFFFFFu, acc[c], 16);
    }

    if (quarter == 0) {                        // lanes 0..7 emit 8 channels each
        float inv = 1.f / (ssum + 1e-16f);     // deg==0: acc=0 -> out=bias (matches ref)
        float4 b0 = ((const float4*)bias)[qx * 2];
        float4 b1 = ((const float4*)bias)[qx * 2 + 1];
        float4 r0, r1;
        r0.x = acc[0] * inv + b0.x; r0.y = acc[1] * inv + b0.y;
        r0.z = acc[2] * inv + b0.z; r0.w = acc[3] * inv + b0.w;
        r1.x = acc[4] * inv + b1.x; r1.y = acc[5] * inv + b1.y;
        r1.z = acc[6] * inv + b1.z; r1.w = acc[7] * inv + b1.w;
        if (do_relu) {
            r0.x = fmaxf(r0.x, 0.f); r0.y = fmaxf(r0.y, 0.f);
            r0.z = fmaxf(r0.z, 0.f); r0.w = fmaxf(r0.w, 0.f);
            r1.x = fmaxf(r1.x, 0.f); r1.y = fmaxf(r1.y, 0.f);
            r1.z = fmaxf(r1.z, 0.f); r1.w = fmaxf(r1.w, 0.f);
        }
        ((float4*)outbuf)[warp * 16 + qx * 2]     = r0;
        ((float4*)outbuf)[warp * 16 + qx * 2 + 1] = r1;
    }
}

// ---------------- launch -------------------------------------------------------------
extern "C" void kernel_launch(void* const* d_in, const int* in_sizes, int n_in,
                              void* d_out, int out_size) {
    // ---- size-driven role assignment (robust to metadata ordering) ----
    int ix = 0, ie = 0, iw1 = 0, iw2 = 0;
    for (int i = 1; i < n_in; i++) if (in_sizes[i] > in_sizes[ix]) ix = i;
    ie = (ix == 0) ? 1 : 0;
    for (int i = 0; i < n_in; i++) if (i != ix && in_sizes[i] > in_sizes[ie]) ie = i;
    iw1 = -1;
    for (int i = 0; i < n_in; i++) {
        if (i == ix || i == ie) continue;
        if (iw1 < 0 || in_sizes[i] > in_sizes[iw1]) iw1 = i;
    }
    iw2 = -1;
    for (int i = 0; i < n_in; i++) {
        if (i == ix || i == ie || i == iw1) continue;
        if (iw2 < 0 || in_sizes[i] > in_sizes[iw2]) iw2 = i;
    }
    int rv[6]; int nrv = 0;
    for (int i = 0; i < n_in && nrv < 6; i++)
        if (i != ix && i != ie && i != iw1 && i != iw2) rv[nrv++] = i;

    int ias1, iad1, ib1, ias2, iad2, ib2;
    if (ix == 0) {  // signature/dict order
        ias1 = rv[0]; iad1 = rv[1]; ib1 = rv[2];
        ias2 = rv[3]; iad2 = rv[4]; ib2 = rv[5];
    } else {        // alphabetical order
        iad1 = rv[0]; iad2 = rv[1]; ias1 = rv[2];
        ias2 = rv[3]; ib1  = rv[4]; ib2  = rv[5];
    }

    const float* x   = (const float*)d_in[ix];
    const void*  ei  = d_in[ie];
    const float* W1  = (const float*)d_in[iw1];
    const float* as1 = (const float*)d_in[ias1];
    const float* ad1 = (const float*)d_in[iad1];
    const float* b1  = (const float*)d_in[ib1];
    const float* W2  = (const float*)d_in[iw2];
    const float* as2 = (const float*)d_in[ias2];
    const float* ad2 = (const float*)d_in[iad2];
    const float* b2  = (const float*)d_in[ib2];
    float*       out = (float*)d_out;

    const int Hd  = in_sizes[ias1];         // 64
    const int Fin = in_sizes[iw1] / Hd;     // 128
    const int N   = in_sizes[ix] / Fin;     // 50000
    const int E   = in_sizes[ie] / 2;       // 800000

    float* p_x2 = nullptr;
    cudaGetSymbolAddress((void**)&p_x2, g_x2);

    const int NGEMM  = (N + 127) / 128;
    const int NING   = (E + 511) / 512;
    const int B_E8   = (E / 8 + 1 + 255) / 256;
    const int B_WARP = (N * 32 + 255) / 256;

    // 6 launches; slot 4 (= ncu capture window) lands on the NEW quarter-warp k_gat.
    k_fat<<<NGEMM + NING, 256>>>(x, W1, as1, ad1, ei, N, E, NGEMM);  // 1
    k_scan<<<1, 1024>>>();                                            // 2
    k_scatter<<<B_E8, 256>>>(E);                                      // 3
    k_gat<<<B_WARP, 256>>>(b1, p_x2, 1, N);                           // 4 <- profiled
    k_gemm2<<<NGEMM, 256>>>(p_x2, W2, as2, ad2, N);                   // 5
    k_gat<<<B_WARP, 256>>>(b2, out, 0, N);                            // 6
}

// round 15
// speedup vs baseline: 1.0460x; 1.0460x over previous
#include <cuda_runtime.h>
#include <cuda_fp16.h>
#include <cstdint>
#include <math_constants.h>

// Fixed dataset shape: N=50000, E=800000, Fin=128, H=C=64
#define NMAX 50048
#define EMAX 800000
#define HC   64

typedef unsigned long long ull;

// ---------------- scratch (__device__ globals; no allocation allowed) --------------
__device__ __half2 g_h2[NMAX * 32];   // h = x @ W, fp16x2 (channel pairs)
__device__ float   g_x2[NMAX * HC];   // layer-2 input (fp32)
__device__ float   g_as[NMAX];        // alpha_src per node
__device__ float   g_ad[NMAX];        // alpha_dst per node
__device__ int     g_src[EMAX];       // edge src
__device__ int     g_dst[EMAX];       // edge dst
__device__ int     g_rank[EMAX];      // rank of edge within its dst row
__device__ int     g_deg[NMAX];       // in-degree histogram (zeroed by k_scan after use)
__device__ int     g_row[NMAX + 4];   // CSR row starts (int4-padded)
__device__ int     g_ssrc[EMAX];      // src ids grouped by dst

// packed f32x2 fma (sm_103a; ptxas never emits FFMA2 from C++)
__device__ __forceinline__ void fma2(ull& acc, ull x2, ull w2) {
    asm("fma.rn.f32x2 %0, %1, %2, %0;" : "+l"(acc) : "l"(x2), "l"(w2));
}
__device__ __forceinline__ ull dup2(float f) {
    ull r;
    asm("mov.b64 %0, {%1, %1};" : "=l"(r) : "f"(f));
    return r;
}

// ---------------- GEMM (R12 proven): prefetch + transposed Xs + FFMA2 ---------------
template <int K>
__launch_bounds__(256)
__global__ void k_gemm(const float* __restrict__ X, const float* __restrict__ W,
                       const float* __restrict__ avs, const float* __restrict__ avd,
                       int N) {
    const int XS = 132;                  // stride: 128 + 4 pad
    __shared__ float Xs[32 * XS];        // [k][row] transposed
    __shared__ float Ws[32 * 64];        // [k][col]
    int tid = threadIdx.x;
    int tx = tid & 15, ty = tid >> 4;
    int row0 = blockIdx.x * 128;

    int xrow = tid >> 3;
    int xk   = (tid & 7) * 4;
    float4 xst[4];
    float4 wst[2];

    auto stage = [&](int k0) {
#pragma unroll
        for (int p = 0; p < 4; p++) {
            int row = row0 + xrow + p * 32;
            xst[p] = (row < N)
                ? *reinterpret_cast<const float4*>(&X[(size_t)row * K + k0 + xk])
                : make_float4(0.f, 0.f, 0.f, 0.f);
        }
#pragma unroll
        for (int j = 0; j < 2; j++) {
            int f = tid + j * 256;
            int k_l = f >> 4, c4 = (f & 15) * 4;
            wst[j] = *reinterpret_cast<const float4*>(&W[(size_t)(k0 + k_l) * 64 + c4]);
        }
    };
    auto commit = [&]() {
#pragma unroll
        for (int p = 0; p < 4; p++) {
            int row_l = xrow + p * 32;
            Xs[(xk + 0) * XS + row_l] = xst[p].x;
            Xs[(xk + 1) * XS + row_l] = xst[p].y;
            Xs[(xk + 2) * XS + row_l] = xst[p].z;
            Xs[(xk + 3) * XS + row_l] = xst[p].w;
        }
#pragma unroll
        for (int j = 0; j < 2; j++) {
            int f = tid + j * 256;
            int k_l = f >> 4, c4 = (f & 15) * 4;
            *reinterpret_cast<float4*>(&Ws[k_l * 64 + c4]) = wst[j];
        }
    };

    ull acc[4][4];
#pragma unroll
    for (int rp = 0; rp < 4; rp++)
#pragma unroll
        for (int c = 0; c < 4; c++) acc[rp][c] = 0ull;

    stage(0);
    const int NT = K / 32;
#pragma unroll
    for (int t = 0; t < NT; t++) {
        commit();
        __syncthreads();
        if (t + 1 < NT) stage((t + 1) * 32);   // LDGs overlap compute below
#pragma unroll
        for (int k = 0; k < 32; k++) {
            ulonglong2 xa = *reinterpret_cast<const ulonglong2*>(&Xs[k * XS + ty * 8]);
            ulonglong2 xb = *reinterpret_cast<const ulonglong2*>(&Xs[k * XS + ty * 8 + 4]);
            float4 wv = *reinterpret_cast<const float4*>(&Ws[k * 64 + tx * 4]);
            ull w2[4];
            w2[0] = dup2(wv.x); w2[1] = dup2(wv.y);
            w2[2] = dup2(wv.z); w2[3] = dup2(wv.w);
#pragma unroll
            for (int c = 0; c < 4; c++) {
                fma2(acc[0][c], xa.x, w2[c]);
                fma2(acc[1][c], xa.y, w2[c]);
                fma2(acc[2][c], xb.x, w2[c]);
                fma2(acc[3][c], xb.y, w2[c]);
            }
        }
        __syncthreads();
    }

    float a[8][4];
#pragma unroll
    for (int rp = 0; rp < 4; rp++)
#pragma unroll
        for (int c = 0; c < 4; c++) {
            float lo, hi;
            asm("mov.b64 {%0, %1}, %2;" : "=f"(lo), "=f"(hi) : "l"(acc[rp][c]));
            a[rp * 2 + 0][c] = lo;
            a[rp * 2 + 1][c] = hi;
        }

    float avs4[4], avd4[4];
#pragma unroll
    for (int j = 0; j < 4; j++) {
        avs4[j] = __ldg(&avs[tx * 4 + j]);
        avd4[j] = __ldg(&avd[tx * 4 + j]);
    }
#pragma unroll
    for (int i = 0; i < 8; i++) {
        int row = row0 + ty * 8 + i;
        float s = a[i][0] * avs4[0] + a[i][1] * avs4[1] + a[i][2] * avs4[2] + a[i][3] * avs4[3];
        float d = a[i][0] * avd4[0] + a[i][1] * avd4[1] + a[i][2] * avd4[2] + a[i][3] * avd4[3];
#pragma unroll
        for (int o = 8; o > 0; o >>= 1) {
            s += __shfl_down_sync(0xFFFFFFFFu, s, o, 16);
            d += __shfl_down_sync(0xFFFFFFFFu, d, o, 16);
        }
        if (tx == 0 && row < N) { g_as[row] = s; g_ad[row] = d; }
        if (row < N) {
            __half2 h01 = __floats2half2_rn(a[i][0], a[i][1]);
            __half2 h23 = __floats2half2_rn(a[i][2], a[i][3]);
            uint2 pk = make_uint2(*reinterpret_cast<uint32_t*>(&h01),
                                  *reinterpret_cast<uint32_t*>(&h23));
            *reinterpret_cast<uint2*>(&g_h2[row * 32 + tx * 2]) = pk;
        }
    }
}

// ---------------- ingest: dtype-detect + convert + histogram + rank -----------------
// 2 edges/thread. Dtype vote: read edge pair AS longlong2 (spans exactly the int32
// buffer bytes — safe both ways).
__global__ void k_ingest(const void* __restrict__ eiv, int E, int N) {
    int i = blockIdx.x * 256 + threadIdx.x;
    int e0 = i * 2;
    long long v0 = 0, v1 = 0;
    int ok = 1;
    if (e0 + 1 < E) {
        longlong2 v = ((const longlong2*)eiv)[i];
        v0 = v.x; v1 = v.y;
        ok = (v0 >= 0 && v0 < (long long)N && v1 >= 0 && v1 < (long long)N) ? 1 : 0;
    } else if (e0 < E) {
        v0 = ((const long long*)eiv)[e0];
        ok = (v0 >= 0 && v0 < (long long)N) ? 1 : 0;
    }
    int all64 = __syncthreads_and(ok);
    if (e0 >= E) return;
    int s0, s1 = 0, d0, d1 = 0;
    int has1 = (e0 + 1 < E);
    if (all64) {
        const long long* e = (const long long*)eiv;
        s0 = (int)v0;
        d0 = (int)e[E + e0];
        if (has1) { s1 = (int)v1; d1 = (int)e[E + e0 + 1]; }
    } else {
        const int* e = (const int*)eiv;
        s0 = e[e0];
        d0 = e[E + e0];
        if (has1) { s1 = e[e0 + 1]; d1 = e[E + e0 + 1]; }
    }
    s0 = min(max(s0, 0), N - 1); d0 = min(max(d0, 0), N - 1);
    g_src[e0] = s0; g_dst[e0] = d0;
    g_rank[e0] = atomicAdd(&g_deg[d0], 1);
    if (has1) {
        s1 = min(max(s1, 0), N - 1); d1 = min(max(d1, 0), N - 1);
        g_src[e0 + 1] = s1; g_dst[e0 + 1] = d1;
        g_rank[e0 + 1] = atomicAdd(&g_deg[d1], 1);
    }
}

// ---------------- scan (self-cleaning: zeroes g_deg after reading) -------------------
__global__ void k_scan() {
    __shared__ int warp_red[32];
    __shared__ int s_carry;
    int tid = threadIdx.x, lane = tid & 31, wid = tid >> 5;
    if (tid == 0) s_carry = 0;
    __syncthreads();
    int4* deg4 = (int4*)g_deg;
    int4* row4 = (int4*)g_row;
    const int total4 = NMAX / 4;
    for (int base = 0; base < total4; base += 1024) {
        int idx = base + tid;
        int4 v = (idx < total4) ? deg4[idx] : make_int4(0, 0, 0, 0);
        if (idx < total4) deg4[idx] = make_int4(0, 0, 0, 0);
        int s = v.x + v.y + v.z + v.w;
        int x = s;
#pragma unroll
        for (int o = 1; o < 32; o <<= 1) {
            int t = __shfl_up_sync(0xFFFFFFFFu, x, o);
            if (lane >= o) x += t;
        }
        if (lane == 31) warp_red[wid] = x;
        __syncthreads();
        if (wid == 0) {
            int w = warp_red[lane];
#pragma unroll
            for (int o = 1; o < 32; o <<= 1) {
                int t = __shfl_up_sync(0xFFFFFFFFu, w, o);
                if (lane >= o) w += t;
            }
            warp_red[lane] = w;
        }
        __syncthreads();
        int wsum = (wid > 0) ? warp_red[wid - 1] : 0;
        int incl = x + wsum;
        int carry = s_carry;
        if (idx < total4) {
            int e0 = carry + incl - s;
            int4 r;
            r.x = e0;
            r.y = e0 + v.x;
            r.z = e0 + v.x + v.y;
            r.w = e0 + v.x + v.y + v.z;
            row4[idx] = r;
        }
        __syncthreads();
        if (tid == 1023) s_carry = carry + incl;
        __syncthreads();
    }
}

// atomic-free scatter, 8 edges/thread (2x int4 loads; MLP=8 on gathers/stores)
__global__ void k_scatter(int E) {
    int i = blockIdx.x * 256 + threadIdx.x;
    int nvec = E >> 3;
    if (i < nvec) {
        const int4* d4 = (const int4*)g_dst;
        const int4* r4 = (const int4*)g_rank;
        const int4* s4 = (const int4*)g_src;
        int4 da = d4[2 * i], db = d4[2 * i + 1];
        int4 ra = r4[2 * i], rb = r4[2 * i + 1];
        int4 sa = s4[2 * i], sb = s4[2 * i + 1];
        int b0 = g_row[da.x], b1 = g_row[da.y], b2 = g_row[da.z], b3 = g_row[da.w];
        int b4 = g_row[db.x], b5 = g_row[db.y], b6 = g_row[db.z], b7 = g_row[db.w];
        g_ssrc[b0 + ra.x] = sa.x;
        g_ssrc[b1 + ra.y] = sa.y;
        g_ssrc[b2 + ra.z] = sa.z;
        g_ssrc[b3 + ra.w] = sa.w;
        g_ssrc[b4 + rb.x] = sb.x;
        g_ssrc[b5 + rb.y] = sb.y;
        g_ssrc[b6 + rb.z] = sb.z;
        g_ssrc[b7 + rb.w] = sb.w;
    } else if (i == nvec) {
        for (int e = nvec * 8; e < E; e++)
            g_ssrc[g_row[g_dst[e]] + g_rank[e]] = g_src[e];
    }
}

// ---------------- fused GAT aggregation (R13 proven): half-warp LDG.64 scheme -------
__global__ void k_gat(const float* __restrict__ bias, float* __restrict__ outbuf,
                      int do_relu, int N) {
    int warp = (blockIdx.x * blockDim.x + threadIdx.x) >> 5;
    int lane = threadIdx.x & 31;
    if (warp >= N) return;
    int beg = g_row[warp], end = g_row[warp + 1];
    float ad = g_ad[warp];
    const uint2* h2v = (const uint2*)g_h2;   // 16 uint2 per node row
    int qx = lane & 15;
    int half = lane >> 4;

    float a0 = 0.f, a1 = 0.f, a2 = 0.f, a3 = 0.f;   // 4 channels: qx*4 .. +3
    float ssum = 0.f;
    for (int base = beg; base < end; base += 32) {
        int i = base + lane;
        float p = 0.f;
        int off = 0;
        if (i < end) {
            int s = g_ssrc[i];
            float e = g_as[s] + ad;
            e = (e > 0.f) ? e : 0.2f * e;      // LeakyReLU(0.2)
            p = __expf(e);
            ssum += p;
            off = s * 16;                       // row offset in uint2 units
        }
        int cnt = min(32, end - base);
        for (int u = 0; u < cnt; u += 8) {      // 8 edges per iter = 4 LDG.64 (MLP 4)
            uint2 hw[4]; float pw[4];
#pragma unroll
            for (int v = 0; v < 4; v++) {
                int j = u + v * 2 + half;                    // this half-warp's edge
                pw[v] = __shfl_sync(0xFFFFFFFFu, p, j);      // p=0 beyond cnt
                int ov = __shfl_sync(0xFFFFFFFFu, off, j);
                hw[v] = h2v[ov + qx];
            }
#pragma unroll
            for (int v = 0; v < 4; v++) {
                float2 fa = __half22float2(*reinterpret_cast<__half2*>(&hw[v].x));
                float2 fb = __half22float2(*reinterpret_cast<__half2*>(&hw[v].y));
                a0 += pw[v] * fa.x;
                a1 += pw[v] * fa.y;
                a2 += pw[v] * fb.x;
                a3 += pw[v] * fb.y;
            }
        }
    }
#pragma unroll
    for (int o = 16; o > 0; o >>= 1)
        ssum += __shfl_xor_sync(0xFFFFFFFFu, ssum, o);

    a0 += __shfl_xor_sync(0xFFFFFFFFu, a0, 16);
    a1 += __shfl_xor_sync(0xFFFFFFFFu, a1, 16);
    a2 += __shfl_xor_sync(0xFFFFFFFFu, a2, 16);
    a3 += __shfl_xor_sync(0xFFFFFFFFu, a3, 16);

    if (half == 0) {
        float inv = 1.f / (ssum + 1e-16f);   // deg==0: acc=0 -> out=bias, matches ref
        float4 bv = ((const float4*)bias)[qx];
        float4 r;
        r.x = a0 * inv + bv.x;
        r.y = a1 * inv + bv.y;
        r.z = a2 * inv + bv.z;
        r.w = a3 * inv + bv.w;
        if (do_relu) {
            r.x = fmaxf(r.x, 0.f); r.y = fmaxf(r.y, 0.f);
            r.z = fmaxf(r.z, 0.f); r.w = fmaxf(r.w, 0.f);
        }
        ((float4*)outbuf)[warp * 16 + qx] = r;
    }
}

// ---------------- launch -------------------------------------------------------------
extern "C" void kernel_launch(void* const* d_in, const int* in_sizes, int n_in,
                              void* d_out, int out_size) {
    // ---- size-driven role assignment (robust to metadata ordering) ----
    int ix = 0, ie = 0, iw1 = 0, iw2 = 0;
    for (int i = 1; i < n_in; i++) if (in_sizes[i] > in_sizes[ix]) ix = i;
    ie = (ix == 0) ? 1 : 0;
    for (int i = 0; i < n_in; i++) if (i != ix && in_sizes[i] > in_sizes[ie]) ie = i;
    iw1 = -1;
    for (int i = 0; i < n_in; i++) {
        if (i == ix || i == ie) continue;
        if (iw1 < 0 || in_sizes[i] > in_sizes[iw1]) iw1 = i;
    }
    iw2 = -1;
    for (int i = 0; i < n_in; i++) {
        if (i == ix || i == ie || i == iw1) continue;
        if (iw2 < 0 || in_sizes[i] > in_sizes[iw2]) iw2 = i;
    }
    int rv[6]; int nrv = 0;
    for (int i = 0; i < n_in && nrv < 6; i++)
        if (i != ix && i != ie && i != iw1 && i != iw2) rv[nrv++] = i;

    int ias1, iad1, ib1, ias2, iad2, ib2;
    if (ix == 0) {  // signature/dict order
        ias1 = rv[0]; iad1 = rv[1]; ib1 = rv[2];
        ias2 = rv[3]; iad2 = rv[4]; ib2 = rv[5];
    } else {        // alphabetical order
        iad1 = rv[0]; iad2 = rv[1]; ias1 = rv[2];
        ias2 = rv[3]; ib1  = rv[4]; ib2  = rv[5];
    }

    const float* x   = (const float*)d_in[ix];
    const void*  ei  = d_in[ie];
    const float* W1  = (const float*)d_in[iw1];
    const float* as1 = (const float*)d_in[ias1];
    const float* ad1 = (const float*)d_in[iad1];
    const float* b1  = (const float*)d_in[ib1];
    const float* W2  = (const float*)d_in[iw2];
    const float* as2 = (const float*)d_in[ias2];
    const float* ad2 = (const float*)d_in[iad2];
    const float* b2  = (const float*)d_in[ib2];
    float*       out = (float*)d_out;

    const int Hd  = in_sizes[ias1];         // 64
    const int Fin = in_sizes[iw1] / Hd;     // 128
    const int N   = in_sizes[ix] / Fin;     // 50000
    const int E   = in_sizes[ie] / 2;       // 800000

    float* p_x2 = nullptr;
    cudaGetSymbolAddress((void**)&p_x2, g_x2);

    // side stream + events: created once on the FIRST call (the uncaptured
    // correctness run), reused on every capture/replay — identical work per call.
    static cudaStream_t s2 = nullptr;
    static cudaEvent_t  eF = nullptr, eJ = nullptr;
    if (!s2) {
        cudaStreamCreateWithFlags(&s2, cudaStreamNonBlocking);
        cudaEventCreateWithFlags(&eF, cudaEventDisableTiming);
        cudaEventCreateWithFlags(&eJ, cudaEventDisableTiming);
    }

    const int NGEMM  = (N + 127) / 128;
    const int B_E2   = (E / 2 + 255) / 256;
    const int B_E8   = (E / 8 + 1 + 255) / 256;
    const int B_WARP = (N * 32 + 255) / 256;

    // fork: gemm1 (independent of edges) runs on s2 concurrent with the CSR chain
    cudaEventRecord(eF, 0);
    cudaStreamWaitEvent(s2, eF, 0);
    k_gemm<128><<<NGEMM, 256, 0, s2>>>(x, W1, as1, ad1, N);
    cudaEventRecord(eJ, s2);

    k_ingest<<<B_E2, 256>>>(ei, E, N);
    k_scan<<<1, 1024>>>();
    k_scatter<<<B_E8, 256>>>(E);

    // join: gat1 needs both the CSR (main stream) and h/alpha (s2)
    cudaStreamWaitEvent(0, eJ, 0);
    k_gat<<<B_WARP, 256>>>(b1, p_x2, 1, N);
    k_gemm<64><<<NGEMM, 256>>>(p_x2, W2, as2, ad2, N);
    k_gat<<<B_WARP, 256>>>(b2, out, 0, N);
}